// round 2
// baseline (speedup 1.0000x reference)
#include <cuda_runtime.h>
#include <math.h>
#include <stdint.h>

#define B_ 4
#define T_ 2048
#define C_ 512
#define H_ 8
#define HD_ 64
#define TOPK_ 32
#define BH_ (B_*H_)          // 32
#define ROWS_ (BH_*T_)       // 65536
#define SPIKES_SZ ((size_t)B_*T_*C_)   // 4194304

typedef unsigned long long ull;

// ------------------- f32x2 (FFMA2) helpers: exact fp32 per half -------------------
__device__ __forceinline__ ull pack2(float x, float y) {
    ull r; asm("mov.b64 %0, {%1, %2};" : "=l"(r) : "f"(x), "f"(y)); return r;
}
__device__ __forceinline__ void unpack2(ull p, float& x, float& y) {
    asm("mov.b64 {%0, %1}, %2;" : "=f"(x), "=f"(y) : "l"(p));
}
__device__ __forceinline__ ull ffma2(ull a, ull b, ull c) {
    ull d; asm("fma.rn.f32x2 %0, %1, %2, %3;" : "=l"(d) : "l"(a), "l"(b), "l"(c)); return d;
}

// ------------------- scratch (device globals; no allocation) -------------------
__device__ float g_q[BH_*T_*HD_];        // [bh][t][d]
__device__ float g_k[BH_*T_*HD_];
__device__ float g_v[BH_*T_*HD_];
__device__ float g_topv[ROWS_*TOPK_];
__device__ int   g_topi[ROWS_*TOPK_];
__device__ float g_ctx[B_*T_*C_];        // [b][t][c]
__device__ float g_analog[B_*T_*C_];

// ------------------- GEMM: M=8192, N=512, K=512 (FFMA2 inner loop) -------------------
// MODE 0: qkv projections (3 z-slices, head-layout epilogue)
// MODE 1: out projection (g_ctx @ Wo + bo -> g_analog)
template<int MODE>
__global__ void __launch_bounds__(256) k_gemm(const float* __restrict__ X,
    const float* __restrict__ Wq, const float* __restrict__ Wk, const float* __restrict__ Wv,
    const float* __restrict__ bq, const float* __restrict__ bk, const float* __restrict__ bv)
{
    __shared__ float As[128][33];
    __shared__ float Bs[32][128];

    const float* Xp   = (MODE == 0) ? X : g_ctx;
    const float* W    = (MODE == 0) ? (blockIdx.z == 0 ? Wq : (blockIdx.z == 1 ? Wk : Wv)) : Wq;
    const float* bias = (MODE == 0) ? (blockIdx.z == 0 ? bq : (blockIdx.z == 1 ? bk : bv)) : bq;
    float* O = 0;
    if (MODE == 0) O = (blockIdx.z == 0 ? g_q : (blockIdx.z == 1 ? g_k : g_v));
    else           O = g_analog;

    const int tid = threadIdx.x;
    const int tx = tid & 15, ty = tid >> 4;
    const int m0 = blockIdx.y * 128, n0 = blockIdx.x * 128;

    ull acc2[8][4];
    #pragma unroll
    for (int j = 0; j < 8; j++)
        #pragma unroll
        for (int ii = 0; ii < 4; ii++) acc2[j][ii] = 0ULL;

    for (int k0 = 0; k0 < 512; k0 += 32) {
        #pragma unroll
        for (int it = 0; it < 4; it++) {
            int f4 = tid + 256 * it;
            int r = f4 >> 3, c4 = f4 & 7;
            float4 v = *(const float4*)&Xp[(size_t)(m0 + r) * 512 + k0 + c4 * 4];
            As[r][c4*4+0] = v.x; As[r][c4*4+1] = v.y; As[r][c4*4+2] = v.z; As[r][c4*4+3] = v.w;
        }
        #pragma unroll
        for (int it = 0; it < 4; it++) {
            int f4 = tid + 256 * it;
            int r = f4 >> 5, c4 = f4 & 31;
            *(float4*)&Bs[r][c4*4] = *(const float4*)&W[(size_t)(k0 + r) * 512 + n0 + c4 * 4];
        }
        __syncthreads();

        #pragma unroll 8
        for (int kk = 0; kk < 32; kk++) {
            float a[8], b[8];
            #pragma unroll
            for (int j = 0; j < 8; j++) a[j] = As[ty + 16*j][kk];
            #pragma unroll
            for (int i = 0; i < 8; i++) b[i] = Bs[kk][tx + 16*i];
            ull bb[4];
            #pragma unroll
            for (int ii = 0; ii < 4; ii++) bb[ii] = pack2(b[2*ii], b[2*ii+1]);
            #pragma unroll
            for (int j = 0; j < 8; j++) {
                ull aa = pack2(a[j], a[j]);
                #pragma unroll
                for (int ii = 0; ii < 4; ii++)
                    acc2[j][ii] = ffma2(aa, bb[ii], acc2[j][ii]);
            }
        }
        __syncthreads();
    }

    #pragma unroll
    for (int j = 0; j < 8; j++) {
        int m = m0 + ty + 16*j;
        #pragma unroll
        for (int ii = 0; ii < 4; ii++) {
            float v0, v1;
            unpack2(acc2[j][ii], v0, v1);
            #pragma unroll
            for (int h = 0; h < 2; h++) {
                int n = n0 + tx + 16 * (2*ii + h);
                float val = (h == 0 ? v0 : v1) + bias[n];
                if (MODE == 0) {
                    int b = m >> 11, t = m & 2047;
                    int hh = n >> 6, d = n & 63;
                    O[(((size_t)(b * H_ + hh)) * T_ + t) * HD_ + d] = val;
                } else {
                    O[(size_t)m * 512 + n] = val;
                }
            }
        }
    }
}

// ------------------- fused scores + top-32 + softmax + scatter -------------------
// grid (16 m-tiles, 32 bh), block 256.  Per block: 128 q-rows, loop over 16 k-tiles.
// FFMA2 score tile -> smem -> ballot-insert merge into persistent sorted top-32.
__global__ void __launch_bounds__(256) k_sattn(float* __restrict__ attn_out)
{
    extern __shared__ float sm[];
    float (*Qs)[65]  = (float(*)[65])sm;                    // 128*65
    float (*Ks)[65]  = (float(*)[65])(sm + 128*65);         // 128*65
    float (*Sb)[133] = (float(*)[133])(sm + 2*128*65);      // 128*133
    float* sval = sm + 2*128*65 + 128*133;                  // 128*32
    int*   sidx = (int*)(sval + 128*32);                    // 128*32

    const unsigned FULL = 0xffffffffu;
    const int bh = blockIdx.y;
    const float* Qb = g_q + (size_t)bh * T_ * HD_;
    const float* Kb = g_k + (size_t)bh * T_ * HD_;
    const int tid = threadIdx.x;
    const int tx = tid & 15, ty = tid >> 4;
    const int warp = tid >> 5, lane = tid & 31;
    const int m0 = blockIdx.x * 128;

    // load Q tile once
    #pragma unroll
    for (int it = 0; it < 8; it++) {
        int f4 = tid + 256 * it;
        int r = f4 >> 4, c4 = f4 & 15;
        float4 v = *(const float4*)&Qb[(size_t)(m0 + r) * 64 + c4 * 4];
        Qs[r][c4*4+0] = v.x; Qs[r][c4*4+1] = v.y; Qs[r][c4*4+2] = v.z; Qs[r][c4*4+3] = v.w;
    }
    // init top-k state
    for (int i = tid; i < 128 * 32; i += 256) { sval[i] = -INFINITY; sidx[i] = 0; }
    __syncthreads();

    for (int tile = 0; tile < 16; tile++) {
        const int n0 = tile * 128;
        // load K tile
        #pragma unroll
        for (int it = 0; it < 8; it++) {
            int f4 = tid + 256 * it;
            int r = f4 >> 4, c4 = f4 & 15;
            float4 w = *(const float4*)&Kb[(size_t)(n0 + r) * 64 + c4 * 4];
            Ks[r][c4*4+0] = w.x; Ks[r][c4*4+1] = w.y; Ks[r][c4*4+2] = w.z; Ks[r][c4*4+3] = w.w;
        }
        __syncthreads();

        // compute 128x128 score tile (FFMA2)
        ull acc2[8][4];
        #pragma unroll
        for (int j = 0; j < 8; j++)
            #pragma unroll
            for (int ii = 0; ii < 4; ii++) acc2[j][ii] = 0ULL;

        #pragma unroll 8
        for (int d = 0; d < 64; d++) {
            float a[8], b[8];
            #pragma unroll
            for (int j = 0; j < 8; j++) a[j] = Qs[ty + 16*j][d];
            #pragma unroll
            for (int i = 0; i < 8; i++) b[i] = Ks[tx + 16*i][d];
            ull bb[4];
            #pragma unroll
            for (int ii = 0; ii < 4; ii++) bb[ii] = pack2(b[2*ii], b[2*ii+1]);
            #pragma unroll
            for (int j = 0; j < 8; j++) {
                ull aa = pack2(a[j], a[j]);
                #pragma unroll
                for (int ii = 0; ii < 4; ii++)
                    acc2[j][ii] = ffma2(aa, bb[ii], acc2[j][ii]);
            }
        }

        // stage scaled scores to smem
        #pragma unroll
        for (int j = 0; j < 8; j++)
            #pragma unroll
            for (int ii = 0; ii < 4; ii++) {
                float v0, v1;
                unpack2(acc2[j][ii], v0, v1);
                Sb[ty + 16*j][tx + 16*(2*ii)]   = v0 * 0.125f;
                Sb[ty + 16*j][tx + 16*(2*ii+1)] = v1 * 0.125f;
            }
        __syncthreads();

        // merge tile into per-row sorted top-32 (warp w owns rows w*16..w*16+15)
        for (int rr = 0; rr < 16; rr++) {
            int row = warp * 16 + rr;
            float lv = sval[row * 32 + lane];
            int   li = sidx[row * 32 + lane];
            #pragma unroll
            for (int c = 0; c < 4; c++) {
                float e = Sb[row][c * 32 + lane];
                int idx = n0 + c * 32 + lane;
                float thr = __shfl_sync(FULL, lv, 31);
                unsigned mask = __ballot_sync(FULL, e > thr);
                while (mask) {
                    int src = __ffs(mask) - 1;
                    mask &= mask - 1;
                    float xv = __shfl_sync(FULL, e, src);
                    int   xi = __shfl_sync(FULL, idx, src);
                    unsigned ge = __ballot_sync(FULL, lv >= xv);
                    int pos = __popc(ge);
                    float pv = __shfl_up_sync(FULL, lv, 1);
                    int   pi = __shfl_up_sync(FULL, li, 1);
                    if (lane >= pos) {
                        lv = (lane == pos) ? xv : pv;
                        li = (lane == pos) ? xi : pi;
                    }
                }
            }
            sval[row * 32 + lane] = lv;
            sidx[row * 32 + lane] = li;
        }
        __syncthreads();
    }

    // epilogue: softmax over top-32, write attn row (zeros + scatter), save for context
    for (int rr = 0; rr < 16; rr++) {
        int row = warp * 16 + rr;
        float lv = sval[row * 32 + lane];
        int   li = sidx[row * 32 + lane];
        float mx = __shfl_sync(FULL, lv, 0);
        float p = expf(lv - mx);
        float s = p;
        #pragma unroll
        for (int o = 16; o; o >>= 1) s += __shfl_xor_sync(FULL, s, o);
        p /= s;

        int grow = bh * T_ + m0 + row;
        g_topv[grow * 32 + lane] = p;
        g_topi[grow * 32 + lane] = li;

        float4* dst = (float4*)(attn_out + (size_t)grow * T_);
        float4 z = make_float4(0.f, 0.f, 0.f, 0.f);
        #pragma unroll
        for (int i = lane; i < 512; i += 32) dst[i] = z;
        __syncwarp();
        attn_out[(size_t)grow * T_ + li] = p;
    }
}

// ------------------- sparse context gather (one warp per row) -------------------
__global__ void __launch_bounds__(256) k_context()
{
    const unsigned FULL = 0xffffffffu;
    int warp = threadIdx.x >> 5, lane = threadIdx.x & 31;
    int row = blockIdx.x * 8 + warp;
    int bh = row >> 11, t = row & 2047;
    const float* Vb = g_v + (size_t)bh * T_ * HD_;

    float pj = g_topv[row * 32 + lane];
    int   ij = g_topi[row * 32 + lane];
    float a0 = 0.f, a1 = 0.f;
    #pragma unroll
    for (int j = 0; j < 32; j++) {
        float p = __shfl_sync(FULL, pj, j);
        int  ix = __shfl_sync(FULL, ij, j);
        const float* vr = Vb + (size_t)ix * HD_;
        a0 += p * vr[lane];
        a1 += p * vr[lane + 32];
    }
    int b = bh >> 3, h = bh & 7;
    float* o = g_ctx + ((size_t)(b * T_ + t)) * C_ + h * HD_;
    o[lane] = a0;
    o[lane + 32] = a1;
}

// ------------------- LayerNorm (two-pass, warp per row) -------------------
__global__ void __launch_bounds__(256) k_ln(const float* __restrict__ gamma,
                                            const float* __restrict__ beta)
{
    const unsigned FULL = 0xffffffffu;
    int warp = threadIdx.x >> 5, lane = threadIdx.x & 31;
    int row = blockIdx.x * 8 + warp;
    const float* x = g_analog + (size_t)row * C_;

    float v[16];
    float s = 0.f;
    #pragma unroll
    for (int i = 0; i < 16; i++) { v[i] = x[lane + 32 * i]; s += v[i]; }
    #pragma unroll
    for (int o = 16; o; o >>= 1) s += __shfl_xor_sync(FULL, s, o);
    float mu = s * (1.0f / 512.0f);

    float q = 0.f;
    #pragma unroll
    for (int i = 0; i < 16; i++) { float d = v[i] - mu; q += d * d; }
    #pragma unroll
    for (int o = 16; o; o >>= 1) q += __shfl_xor_sync(FULL, q, o);
    float var = q * (1.0f / 512.0f);
    float inv = 1.0f / sqrtf(var + 1e-5f);

    float* y = g_analog + (size_t)row * C_;
    #pragma unroll
    for (int i = 0; i < 16; i++) {
        int c = lane + 32 * i;
        y[c] = (v[i] - mu) * inv * gamma[c] + beta[c];
    }
}

// ------------------- adaptive LIF readout (one thread per (b,c) chain) -------------------
__global__ void __launch_bounds__(256) k_lif(float* __restrict__ out)
{
    int idx = blockIdx.x * 256 + threadIdx.x;   // 0..2047 -> (b, c)
    int b = idx >> 9, c = idx & 511;
    const float* x = g_analog + (size_t)b * T_ * C_ + c;
    float* o = out + (size_t)b * T_ * C_ + c;

    float vm = 0.f, ad = 0.f;
    #pragma unroll 4
    for (int t = 0; t < T_; t++) {
        float xt = x[(size_t)t * C_];
        vm = 0.9f * vm + xt;
        float th = 1.0f + 0.1f * ad;
        float u = vm - th;
        float sp = (u > 0.0f) ? 1.0f : 0.0f;
        vm = vm - sp * th;
        ad = 0.9f * ad + sp;
        o[(size_t)t * C_] = sp;
    }
}

// ------------------- launch -------------------
extern "C" void kernel_launch(void* const* d_in, const int* in_sizes, int n_in,
                              void* d_out, int out_size)
{
    const float* x     = (const float*)d_in[0];
    const float* Wq    = (const float*)d_in[1];
    const float* bq    = (const float*)d_in[2];
    const float* Wk    = (const float*)d_in[3];
    const float* bk    = (const float*)d_in[4];
    const float* Wv    = (const float*)d_in[5];
    const float* bv    = (const float*)d_in[6];
    const float* Wo    = (const float*)d_in[7];
    const float* bo    = (const float*)d_in[8];
    const float* gamma = (const float*)d_in[9];
    const float* beta  = (const float*)d_in[10];

    float* out      = (float*)d_out;
    float* out_attn = out + SPIKES_SZ;

    // 1) QKV projections -> g_q/g_k/g_v in [bh][t][d] layout
    k_gemm<0><<<dim3(4, 64, 3), 256>>>(x, Wq, Wk, Wv, bq, bk, bv);

    // 2+3) fused scores + top-32 + softmax + scatter
    const int smem_sattn = (2 * 128 * 65 + 128 * 133 + 128 * 32 * 2) * 4;  // 167424 B
    cudaFuncSetAttribute(k_sattn, cudaFuncAttributeMaxDynamicSharedMemorySize, smem_sattn);
    k_sattn<<<dim3(16, 32), 256, smem_sattn>>>(out_attn);

    // 4) sparse context
    k_context<<<ROWS_ / 8, 256>>>();

    // 5) out projection -> g_analog
    k_gemm<1><<<dim3(4, 64, 1), 256>>>(nullptr, Wo, Wo, Wo, bo, bo, bo);

    // 6) layernorm (in place)
    k_ln<<<(B_ * T_) / 8, 256>>>(gamma, beta);

    // 7) LIF readout -> spikes output
    k_lif<<<8, 256>>>(out);
}

// round 3
// speedup vs baseline: 1.4822x; 1.4822x over previous
#include <cuda_runtime.h>
#include <math.h>
#include <stdint.h>

#define B_ 4
#define T_ 2048
#define C_ 512
#define H_ 8
#define HD_ 64
#define TOPK_ 32
#define BH_ (B_*H_)          // 32
#define ROWS_ (BH_*T_)       // 65536
#define SPIKES_SZ ((size_t)B_*T_*C_)   // 4194304

// ------------------- scratch (device globals; no allocation) -------------------
__device__ float g_q[BH_*T_*HD_];        // [bh][t][d]
__device__ float g_k[BH_*T_*HD_];
__device__ float g_v[BH_*T_*HD_];
__device__ float g_scores[(size_t)ROWS_*T_];   // 537MB [row][tk]
__device__ float g_topv[ROWS_*TOPK_];
__device__ int   g_topi[ROWS_*TOPK_];
__device__ float g_ctx[B_*T_*C_];        // [b][t][c]
__device__ float g_analog[B_*T_*C_];

// ------------------- GEMM: M=8192, N=512, K=512 -------------------
// k-major smem, LDS.128 reads, contiguous 8x8 microtile per thread.
// MODE 0: qkv projections (3 z-slices, head-layout epilogue)
// MODE 1: out projection (g_ctx @ Wo + bo -> g_analog)
template<int MODE>
__global__ void __launch_bounds__(256) k_gemm(const float* __restrict__ X,
    const float* __restrict__ Wq, const float* __restrict__ Wk, const float* __restrict__ Wv,
    const float* __restrict__ bq, const float* __restrict__ bk, const float* __restrict__ bv)
{
    __shared__ float At[32][132];   // [k][m], stride 132 floats = 33*16B (aligned rows)
    __shared__ float Bs[32][132];   // [k][n]

    const float* Xp   = (MODE == 0) ? X : g_ctx;
    const float* W    = (MODE == 0) ? (blockIdx.z == 0 ? Wq : (blockIdx.z == 1 ? Wk : Wv)) : Wq;
    const float* bias = (MODE == 0) ? (blockIdx.z == 0 ? bq : (blockIdx.z == 1 ? bk : bv)) : bq;
    float* O = 0;
    if (MODE == 0) O = (blockIdx.z == 0 ? g_q : (blockIdx.z == 1 ? g_k : g_v));
    else           O = g_analog;

    const int tid = threadIdx.x;
    const int tx = tid & 15, ty = tid >> 4;
    const int m0 = blockIdx.y * 128, n0 = blockIdx.x * 128;

    float acc[8][8];
    #pragma unroll
    for (int j = 0; j < 8; j++)
        #pragma unroll
        for (int i = 0; i < 8; i++) acc[j][i] = 0.0f;

    for (int k0 = 0; k0 < 512; k0 += 32) {
        // A tile 128x32 -> At[k][m] (transposed scalar stores)
        #pragma unroll
        for (int it = 0; it < 4; it++) {
            int f4 = tid + 256 * it;
            int r = f4 >> 3, c = f4 & 7;            // r: m-row, c: k-group
            float4 v = *(const float4*)&Xp[(size_t)(m0 + r) * 512 + k0 + c * 4];
            At[c*4+0][r] = v.x; At[c*4+1][r] = v.y; At[c*4+2][r] = v.z; At[c*4+3][r] = v.w;
        }
        // B tile 32x128 -> Bs[k][n] (vectorized)
        #pragma unroll
        for (int it = 0; it < 4; it++) {
            int f4 = tid + 256 * it;
            int r = f4 >> 5, c4 = f4 & 31;
            *(float4*)&Bs[r][c4*4] = *(const float4*)&W[(size_t)(k0 + r) * 512 + n0 + c4 * 4];
        }
        __syncthreads();

        #pragma unroll 8
        for (int kk = 0; kk < 32; kk++) {
            float4 a0 = *(const float4*)&At[kk][ty*8];
            float4 a1 = *(const float4*)&At[kk][ty*8+4];
            float4 b0 = *(const float4*)&Bs[kk][tx*8];
            float4 b1 = *(const float4*)&Bs[kk][tx*8+4];
            float a[8] = {a0.x,a0.y,a0.z,a0.w,a1.x,a1.y,a1.z,a1.w};
            float b[8] = {b0.x,b0.y,b0.z,b0.w,b1.x,b1.y,b1.z,b1.w};
            #pragma unroll
            for (int j = 0; j < 8; j++)
                #pragma unroll
                for (int i = 0; i < 8; i++)
                    acc[j][i] += a[j] * b[i];
        }
        __syncthreads();
    }

    #pragma unroll
    for (int j = 0; j < 8; j++) {
        int m = m0 + ty*8 + j;
        #pragma unroll
        for (int g = 0; g < 2; g++) {
            int n = n0 + tx*8 + g*4;
            float4 val;
            val.x = acc[j][g*4+0] + bias[n+0];
            val.y = acc[j][g*4+1] + bias[n+1];
            val.z = acc[j][g*4+2] + bias[n+2];
            val.w = acc[j][g*4+3] + bias[n+3];
            if (MODE == 0) {
                int b = m >> 11, t = m & 2047;
                int h = n >> 6, d = n & 63;    // 4 consecutive d within one head
                *(float4*)&O[(((size_t)(b * H_ + h)) * T_ + t) * HD_ + d] = val;
            } else {
                *(float4*)&O[(size_t)m * 512 + n] = val;
            }
        }
    }
}

// ------------------- scores: per-bh 2048x2048x64 GEMM, *SCALE -------------------
__global__ void __launch_bounds__(256) k_scores()
{
    extern __shared__ float sm[];
    float (*Qt)[132] = (float(*)[132])sm;                 // [d][m] 64x132
    float (*Kt)[132] = (float(*)[132])(sm + 64 * 132);    // [d][n] 64x132

    const int bh = blockIdx.z;
    const float* Qb = g_q + (size_t)bh * T_ * HD_;
    const float* Kb = g_k + (size_t)bh * T_ * HD_;
    const int tid = threadIdx.x;
    const int tx = tid & 15, ty = tid >> 4;
    const int m0 = blockIdx.y * 128, n0 = blockIdx.x * 128;

    // transposed loads: [t][d] -> [d][t-within-tile]
    #pragma unroll
    for (int it = 0; it < 8; it++) {
        int f4 = tid + 256 * it;
        int r = f4 >> 4, c = f4 & 15;               // r: row, c: d-group
        float4 v = *(const float4*)&Qb[(size_t)(m0 + r) * 64 + c * 4];
        Qt[c*4+0][r] = v.x; Qt[c*4+1][r] = v.y; Qt[c*4+2][r] = v.z; Qt[c*4+3][r] = v.w;
        float4 w = *(const float4*)&Kb[(size_t)(n0 + r) * 64 + c * 4];
        Kt[c*4+0][r] = w.x; Kt[c*4+1][r] = w.y; Kt[c*4+2][r] = w.z; Kt[c*4+3][r] = w.w;
    }
    __syncthreads();

    float acc[8][8];
    #pragma unroll
    for (int j = 0; j < 8; j++)
        #pragma unroll
        for (int i = 0; i < 8; i++) acc[j][i] = 0.0f;

    #pragma unroll 8
    for (int d = 0; d < 64; d++) {
        float4 a0 = *(const float4*)&Qt[d][ty*8];
        float4 a1 = *(const float4*)&Qt[d][ty*8+4];
        float4 b0 = *(const float4*)&Kt[d][tx*8];
        float4 b1 = *(const float4*)&Kt[d][tx*8+4];
        float a[8] = {a0.x,a0.y,a0.z,a0.w,a1.x,a1.y,a1.z,a1.w};
        float b[8] = {b0.x,b0.y,b0.z,b0.w,b1.x,b1.y,b1.z,b1.w};
        #pragma unroll
        for (int j = 0; j < 8; j++)
            #pragma unroll
            for (int i = 0; i < 8; i++)
                acc[j][i] += a[j] * b[i];
    }

    float* Sb = g_scores + (size_t)bh * T_ * T_;
    #pragma unroll
    for (int j = 0; j < 8; j++) {
        int m = m0 + ty*8 + j;
        #pragma unroll
        for (int g = 0; g < 2; g++) {
            int n = n0 + tx*8 + g*4;
            float4 val;
            val.x = acc[j][g*4+0] * 0.125f;
            val.y = acc[j][g*4+1] * 0.125f;
            val.z = acc[j][g*4+2] * 0.125f;
            val.w = acc[j][g*4+3] * 0.125f;
            *(float4*)&Sb[(size_t)m * T_ + n] = val;
        }
    }
}

// ------------------- top-32 + softmax + scatter (one warp per row) -------------------
__global__ void __launch_bounds__(256) k_topk(float* __restrict__ attn_out)
{
    const unsigned FULL = 0xffffffffu;
    int warp = threadIdx.x >> 5, lane = threadIdx.x & 31;
    int row = blockIdx.x * 8 + warp;
    const float* r = g_scores + (size_t)row * T_;

    float lv = -INFINITY;  // lane holds slot `lane` of descending sorted top-32
    int   li = 0;

    for (int c = 0; c < 64; c++) {
        int idx = c * 32 + lane;
        float e = r[idx];
        float thr = __shfl_sync(FULL, lv, 31);        // current min of list
        unsigned mask = __ballot_sync(FULL, e > thr);
        while (mask) {
            int src = __ffs(mask) - 1;
            mask &= mask - 1;
            float xv = __shfl_sync(FULL, e, src);
            int   xi = __shfl_sync(FULL, idx, src);
            unsigned ge = __ballot_sync(FULL, lv >= xv);   // entries ranked above x (stable)
            int pos = __popc(ge);
            float pv = __shfl_up_sync(FULL, lv, 1);
            int   pi = __shfl_up_sync(FULL, li, 1);
            if (lane >= pos) {
                lv = (lane == pos) ? xv : pv;
                li = (lane == pos) ? xi : pi;
            }
        }
    }

    // softmax over the 32 selected values (lane 0 holds the max)
    float mx = __shfl_sync(FULL, lv, 0);
    float p = expf(lv - mx);
    float s = p;
    #pragma unroll
    for (int o = 16; o; o >>= 1) s += __shfl_xor_sync(FULL, s, o);
    p /= s;

    g_topv[row * 32 + lane] = p;
    g_topi[row * 32 + lane] = li;

    // write full attn row: zeros then scatter
    float4* dst = (float4*)(attn_out + (size_t)row * T_);
    float4 z = make_float4(0.f, 0.f, 0.f, 0.f);
    #pragma unroll
    for (int i = lane; i < 512; i += 32) dst[i] = z;
    __syncwarp();
    attn_out[(size_t)row * T_ + li] = p;
}

// ------------------- sparse context gather (one warp per row) -------------------
__global__ void __launch_bounds__(256) k_context()
{
    const unsigned FULL = 0xffffffffu;
    int warp = threadIdx.x >> 5, lane = threadIdx.x & 31;
    int row = blockIdx.x * 8 + warp;
    int bh = row >> 11, t = row & 2047;
    const float* Vb = g_v + (size_t)bh * T_ * HD_;

    float pj = g_topv[row * 32 + lane];
    int   ij = g_topi[row * 32 + lane];
    float a0 = 0.f, a1 = 0.f;
    #pragma unroll
    for (int j = 0; j < 32; j++) {
        float p = __shfl_sync(FULL, pj, j);
        int  ix = __shfl_sync(FULL, ij, j);
        const float* vr = Vb + (size_t)ix * HD_;
        a0 += p * vr[lane];
        a1 += p * vr[lane + 32];
    }
    int b = bh >> 3, h = bh & 7;
    float* o = g_ctx + ((size_t)(b * T_ + t)) * C_ + h * HD_;
    o[lane] = a0;
    o[lane + 32] = a1;
}

// ------------------- LayerNorm (two-pass, warp per row) -------------------
__global__ void __launch_bounds__(256) k_ln(const float* __restrict__ gamma,
                                            const float* __restrict__ beta)
{
    const unsigned FULL = 0xffffffffu;
    int warp = threadIdx.x >> 5, lane = threadIdx.x & 31;
    int row = blockIdx.x * 8 + warp;
    const float* x = g_analog + (size_t)row * C_;

    float v[16];
    float s = 0.f;
    #pragma unroll
    for (int i = 0; i < 16; i++) { v[i] = x[lane + 32 * i]; s += v[i]; }
    #pragma unroll
    for (int o = 16; o; o >>= 1) s += __shfl_xor_sync(FULL, s, o);
    float mu = s * (1.0f / 512.0f);

    float q = 0.f;
    #pragma unroll
    for (int i = 0; i < 16; i++) { float d = v[i] - mu; q += d * d; }
    #pragma unroll
    for (int o = 16; o; o >>= 1) q += __shfl_xor_sync(FULL, q, o);
    float var = q * (1.0f / 512.0f);
    float inv = 1.0f / sqrtf(var + 1e-5f);

    float* y = g_analog + (size_t)row * C_;
    #pragma unroll
    for (int i = 0; i < 16; i++) {
        int c = lane + 32 * i;
        y[c] = (v[i] - mu) * inv * gamma[c] + beta[c];
    }
}

// ------------------- adaptive LIF readout (one thread per (b,c) chain) -------------------
__global__ void __launch_bounds__(256) k_lif(float* __restrict__ out)
{
    int idx = blockIdx.x * 256 + threadIdx.x;   // 0..2047 -> (b, c)
    int b = idx >> 9, c = idx & 511;
    const float* x = g_analog + (size_t)b * T_ * C_ + c;
    float* o = out + (size_t)b * T_ * C_ + c;

    float vm = 0.f, ad = 0.f;
    #pragma unroll 4
    for (int t = 0; t < T_; t++) {
        float xt = x[(size_t)t * C_];
        vm = 0.9f * vm + xt;
        float th = 1.0f + 0.1f * ad;
        float u = vm - th;
        float sp = (u > 0.0f) ? 1.0f : 0.0f;
        vm = vm - sp * th;
        ad = 0.9f * ad + sp;
        o[(size_t)t * C_] = sp;
    }
}

// ------------------- launch -------------------
extern "C" void kernel_launch(void* const* d_in, const int* in_sizes, int n_in,
                              void* d_out, int out_size)
{
    const float* x     = (const float*)d_in[0];
    const float* Wq    = (const float*)d_in[1];
    const float* bq    = (const float*)d_in[2];
    const float* Wk    = (const float*)d_in[3];
    const float* bk    = (const float*)d_in[4];
    const float* Wv    = (const float*)d_in[5];
    const float* bv    = (const float*)d_in[6];
    const float* Wo    = (const float*)d_in[7];
    const float* bo    = (const float*)d_in[8];
    const float* gamma = (const float*)d_in[9];
    const float* beta  = (const float*)d_in[10];

    float* out      = (float*)d_out;
    float* out_attn = out + SPIKES_SZ;

    // 1) QKV projections -> g_q/g_k/g_v in [bh][t][d] layout
    k_gemm<0><<<dim3(4, 64, 3), 256>>>(x, Wq, Wk, Wv, bq, bk, bv);

    // 2) scores = Q K^T * scale  (batched over 32 bh)
    const int smem_scores = 2 * 64 * 132 * 4;   // 67584 B
    cudaFuncSetAttribute(k_scores, cudaFuncAttributeMaxDynamicSharedMemorySize, smem_scores);
    k_scores<<<dim3(16, 16, 32), 256, smem_scores>>>();

    // 3) top-32 + softmax + scatter into attn output
    k_topk<<<ROWS_ / 8, 256>>>(out_attn);

    // 4) sparse context
    k_context<<<ROWS_ / 8, 256>>>();

    // 5) out projection -> g_analog
    k_gemm<1><<<dim3(4, 64, 1), 256>>>(nullptr, Wo, Wo, Wo, bo, bo, bo);

    // 6) layernorm (in place)
    k_ln<<<(B_ * T_) / 8, 256>>>(gamma, beta);

    // 7) LIF readout -> spikes output
    k_lif<<<8, 256>>>(out);
}

// round 6
// speedup vs baseline: 1.5211x; 1.0263x over previous
#include <cuda_runtime.h>
#include <math.h>
#include <stdint.h>

#define B_ 4
#define T_ 2048
#define C_ 512
#define H_ 8
#define HD_ 64
#define TOPK_ 32
#define BH_ (B_*H_)          // 32
#define ROWS_ (BH_*T_)       // 65536
#define SPIKES_SZ ((size_t)B_*T_*C_)   // 4194304

// ------------------- scratch (device globals; no allocation) -------------------
__device__ float g_q[BH_*T_*HD_];        // [bh][t][d]
__device__ float g_k[BH_*T_*HD_];
__device__ float g_v[BH_*T_*HD_];
__device__ float g_scores[(size_t)ROWS_*T_];   // 537MB [row][tk]
__device__ float g_topv[ROWS_*TOPK_];
__device__ int   g_topi[ROWS_*TOPK_];
__device__ float g_ctx[B_*T_*C_];        // [b][t][c]
__device__ float g_analog[B_*T_*C_];

// ------------------- GEMM: M=8192, N=512, K=512, double-buffered -------------------
// Round-1 conflict-free smem layout + register-prefetch double buffering.
// MODE 0: qkv projections (3 z-slices, head-layout epilogue)
// MODE 1: out projection (g_ctx @ Wo + bo -> g_analog)
template<int MODE>
__global__ void __launch_bounds__(256, 2) k_gemm(const float* __restrict__ X,
    const float* __restrict__ Wq, const float* __restrict__ Wk, const float* __restrict__ Wv,
    const float* __restrict__ bq, const float* __restrict__ bk, const float* __restrict__ bv)
{
    extern __shared__ float smg[];
    float (*As)[128][33] = (float(*)[128][33])smg;               // 2 x 128 x 33
    float (*Bs)[32][128] = (float(*)[32][128])(smg + 2*128*33);  // 2 x 32 x 128

    const float* Xp   = (MODE == 0) ? X : g_ctx;
    const float* W    = (MODE == 0) ? (blockIdx.z == 0 ? Wq : (blockIdx.z == 1 ? Wk : Wv)) : Wq;
    const float* bias = (MODE == 0) ? (blockIdx.z == 0 ? bq : (blockIdx.z == 1 ? bk : bv)) : bq;
    float* O = 0;
    if (MODE == 0) O = (blockIdx.z == 0 ? g_q : (blockIdx.z == 1 ? g_k : g_v));
    else           O = g_analog;

    const int tid = threadIdx.x;
    const int tx = tid & 15, ty = tid >> 4;
    const int m0 = blockIdx.y * 128, n0 = blockIdx.x * 128;

    // per-thread load coords (fixed across iterations)
    const int ar = tid >> 3, ac = tid & 7;     // A: row ar(+128 stride? no: 4 chunks below)
    const int br = tid >> 5, bc4 = tid & 31;   // B

    float acc[8][8];
    #pragma unroll
    for (int j = 0; j < 8; j++)
        #pragma unroll
        for (int i = 0; i < 8; i++) acc[j][i] = 0.0f;

    // prologue: load tile 0 straight into buffer 0
    #pragma unroll
    for (int it = 0; it < 4; it++) {
        int f4 = tid + 256 * it;
        int r = f4 >> 3, c = f4 & 7;
        float4 v = *(const float4*)&Xp[(size_t)(m0 + r) * 512 + c * 4];
        As[0][r][c*4+0] = v.x; As[0][r][c*4+1] = v.y; As[0][r][c*4+2] = v.z; As[0][r][c*4+3] = v.w;
    }
    #pragma unroll
    for (int it = 0; it < 4; it++) {
        int f4 = tid + 256 * it;
        int r = f4 >> 5, c4 = f4 & 31;
        *(float4*)&Bs[0][r][c4*4] = *(const float4*)&W[(size_t)r * 512 + n0 + c4 * 4];
    }
    __syncthreads();

    int buf = 0;
    for (int k0 = 0; k0 < 512; k0 += 32, buf ^= 1) {
        const int kn = k0 + 32;
        float4 rA[4], rB[4];
        if (kn < 512) {
            #pragma unroll
            for (int it = 0; it < 4; it++) {
                int f4 = tid + 256 * it;
                int r = f4 >> 3, c = f4 & 7;
                rA[it] = *(const float4*)&Xp[(size_t)(m0 + r) * 512 + kn + c * 4];
            }
            #pragma unroll
            for (int it = 0; it < 4; it++) {
                int f4 = tid + 256 * it;
                int r = f4 >> 5, c4 = f4 & 31;
                rB[it] = *(const float4*)&W[(size_t)(kn + r) * 512 + n0 + c4 * 4];
            }
        }

        // compute current buffer (identical arithmetic order to round-1)
        #pragma unroll 8
        for (int kk = 0; kk < 32; kk++) {
            float a[8], b[8];
            #pragma unroll
            for (int j = 0; j < 8; j++) a[j] = As[buf][ty + 16*j][kk];
            #pragma unroll
            for (int i = 0; i < 8; i++) b[i] = Bs[buf][kk][tx + 16*i];
            #pragma unroll
            for (int j = 0; j < 8; j++)
                #pragma unroll
                for (int i = 0; i < 8; i++)
                    acc[j][i] += a[j] * b[i];
        }

        if (kn < 512) {
            #pragma unroll
            for (int it = 0; it < 4; it++) {
                int f4 = tid + 256 * it;
                int r = f4 >> 3, c = f4 & 7;
                As[buf^1][r][c*4+0] = rA[it].x; As[buf^1][r][c*4+1] = rA[it].y;
                As[buf^1][r][c*4+2] = rA[it].z; As[buf^1][r][c*4+3] = rA[it].w;
            }
            #pragma unroll
            for (int it = 0; it < 4; it++) {
                int f4 = tid + 256 * it;
                int r = f4 >> 5, c4 = f4 & 31;
                *(float4*)&Bs[buf^1][r][c4*4] = rB[it];
            }
        }
        __syncthreads();
    }

    #pragma unroll
    for (int j = 0; j < 8; j++) {
        int m = m0 + ty + 16*j;
        #pragma unroll
        for (int i = 0; i < 8; i++) {
            int n = n0 + tx + 16*i;
            float val = acc[j][i] + bias[n];
            if (MODE == 0) {
                int b = m >> 11, t = m & 2047;
                int h = n >> 6, d = n & 63;
                O[(((size_t)(b * H_ + h)) * T_ + t) * HD_ + d] = val;
            } else {
                O[(size_t)m * 512 + n] = val;
            }
        }
    }
}

// ------------------- scores: per-bh 2048x2048x64 GEMM, *SCALE, + attn zero-fill -------------------
__global__ void __launch_bounds__(256) k_scores(float* __restrict__ attn_out)
{
    extern __shared__ float sm[];
    float (*Qs)[65] = (float(*)[65])sm;               // 128 x 65
    float (*Ks)[65] = (float(*)[65])(sm + 128 * 65);  // 128 x 65

    const int bh = blockIdx.z;
    const float* Qb = g_q + (size_t)bh * T_ * HD_;
    const float* Kb = g_k + (size_t)bh * T_ * HD_;
    const int tid = threadIdx.x;
    const int tx = tid & 15, ty = tid >> 4;
    const int m0 = blockIdx.y * 128, n0 = blockIdx.x * 128;

    #pragma unroll
    for (int it = 0; it < 8; it++) {   // 2048 float4 per tile
        int f4 = tid + 256 * it;
        int r = f4 >> 4, c4 = f4 & 15;
        float4 v = *(const float4*)&Qb[(size_t)(m0 + r) * 64 + c4 * 4];
        Qs[r][c4*4+0] = v.x; Qs[r][c4*4+1] = v.y; Qs[r][c4*4+2] = v.z; Qs[r][c4*4+3] = v.w;
        float4 w = *(const float4*)&Kb[(size_t)(n0 + r) * 64 + c4 * 4];
        Ks[r][c4*4+0] = w.x; Ks[r][c4*4+1] = w.y; Ks[r][c4*4+2] = w.z; Ks[r][c4*4+3] = w.w;
    }
    __syncthreads();

    float acc[8][8];
    #pragma unroll
    for (int j = 0; j < 8; j++)
        #pragma unroll
        for (int i = 0; i < 8; i++) acc[j][i] = 0.0f;

    #pragma unroll 8
    for (int d = 0; d < 64; d++) {
        float a[8], b[8];
        #pragma unroll
        for (int j = 0; j < 8; j++) a[j] = Qs[ty + 16*j][d];
        #pragma unroll
        for (int i = 0; i < 8; i++) b[i] = Ks[tx + 16*i][d];
        #pragma unroll
        for (int j = 0; j < 8; j++)
            #pragma unroll
            for (int i = 0; i < 8; i++)
                acc[j][i] += a[j] * b[i];
    }

    float* Sb = g_scores + (size_t)bh * T_ * T_;
    const float4 z = make_float4(0.f, 0.f, 0.f, 0.f);
    #pragma unroll
    for (int j = 0; j < 8; j++) {
        int m = m0 + ty + 16*j;
        #pragma unroll
        for (int i = 0; i < 8; i++) {
            int n = n0 + tx + 16*i;
            Sb[(size_t)m * T_ + n] = acc[j][i] * 0.125f;
        }
        // zero-fill this block's tile of the attn output (hidden under compute of other CTAs)
        size_t grow = (size_t)(bh * T_ + m);
        float4* dst = (float4*)(attn_out + grow * T_ + n0);
        dst[tx*2]   = z;
        dst[tx*2+1] = z;
    }
}

// ------------------- top-32 + softmax + scatter (one warp per row, MLP=8 prefetch) -------------------
__global__ void __launch_bounds__(256) k_topk(float* __restrict__ attn_out)
{
    const unsigned FULL = 0xffffffffu;
    int warp = threadIdx.x >> 5, lane = threadIdx.x & 31;
    int row = blockIdx.x * 8 + warp;
    const float* r = g_scores + (size_t)row * T_;

    float lv = -INFINITY;  // lane holds slot `lane` of descending sorted top-32
    int   li = 0;

    for (int cb = 0; cb < 64; cb += 8) {
        float e8[8];
        #pragma unroll
        for (int j = 0; j < 8; j++) e8[j] = r[(cb + j) * 32 + lane];   // 8 loads in flight

        #pragma unroll
        for (int j = 0; j < 8; j++) {
            float e = e8[j];
            int idx = (cb + j) * 32 + lane;
            float thr = __shfl_sync(FULL, lv, 31);        // current min of list
            unsigned mask = __ballot_sync(FULL, e > thr);
            while (mask) {
                int src = __ffs(mask) - 1;
                mask &= mask - 1;
                float xv = __shfl_sync(FULL, e, src);
                int   xi = __shfl_sync(FULL, idx, src);
                unsigned ge = __ballot_sync(FULL, lv >= xv);   // entries ranked above x (stable)
                int pos = __popc(ge);
                float pv = __shfl_up_sync(FULL, lv, 1);
                int   pi = __shfl_up_sync(FULL, li, 1);
                if (lane >= pos) {
                    lv = (lane == pos) ? xv : pv;
                    li = (lane == pos) ? xi : pi;
                }
            }
        }
    }

    // softmax over the 32 selected values (lane 0 holds the max)
    float mx = __shfl_sync(FULL, lv, 0);
    float p = expf(lv - mx);
    float s = p;
    #pragma unroll
    for (int o = 16; o; o >>= 1) s += __shfl_xor_sync(FULL, s, o);
    p /= s;

    g_topv[row * 32 + lane] = p;
    g_topi[row * 32 + lane] = li;

    // row already zeroed by k_scores; just scatter
    attn_out[(size_t)row * T_ + li] = p;
}

// ------------------- sparse context gather (one warp per row) -------------------
__global__ void __launch_bounds__(256) k_context()
{
    const unsigned FULL = 0xffffffffu;
    int warp = threadIdx.x >> 5, lane = threadIdx.x & 31;
    int row = blockIdx.x * 8 + warp;
    int bh = row >> 11, t = row & 2047;
    const float* Vb = g_v + (size_t)bh * T_ * HD_;

    float pj = g_topv[row * 32 + lane];
    int   ij = g_topi[row * 32 + lane];
    float a0 = 0.f, a1 = 0.f;
    #pragma unroll
    for (int j = 0; j < 32; j++) {
        float p = __shfl_sync(FULL, pj, j);
        int  ix = __shfl_sync(FULL, ij, j);
        const float* vr = Vb + (size_t)ix * HD_;
        a0 += p * vr[lane];
        a1 += p * vr[lane + 32];
    }
    int b = bh >> 3, h = bh & 7;
    float* o = g_ctx + ((size_t)(b * T_ + t)) * C_ + h * HD_;
    o[lane] = a0;
    o[lane + 32] = a1;
}

// ------------------- LayerNorm (two-pass, warp per row) -------------------
__global__ void __launch_bounds__(256) k_ln(const float* __restrict__ gamma,
                                            const float* __restrict__ beta)
{
    const unsigned FULL = 0xffffffffu;
    int warp = threadIdx.x >> 5, lane = threadIdx.x & 31;
    int row = blockIdx.x * 8 + warp;
    const float* x = g_analog + (size_t)row * C_;

    float v[16];
    float s = 0.f;
    #pragma unroll
    for (int i = 0; i < 16; i++) { v[i] = x[lane + 32 * i]; s += v[i]; }
    #pragma unroll
    for (int o = 16; o; o >>= 1) s += __shfl_xor_sync(FULL, s, o);
    float mu = s * (1.0f / 512.0f);

    float q = 0.f;
    #pragma unroll
    for (int i = 0; i < 16; i++) { float d = v[i] - mu; q += d * d; }
    #pragma unroll
    for (int o = 16; o; o >>= 1) q += __shfl_xor_sync(FULL, q, o);
    float var = q * (1.0f / 512.0f);
    float inv = 1.0f / sqrtf(var + 1e-5f);

    float* y = g_analog + (size_t)row * C_;
    #pragma unroll
    for (int i = 0; i < 16; i++) {
        int c = lane + 32 * i;
        y[c] = (v[i] - mu) * inv * gamma[c] + beta[c];
    }
}

// ------------------- adaptive LIF readout (one thread per (b,c) chain) -------------------
__global__ void __launch_bounds__(256) k_lif(float* __restrict__ out)
{
    int idx = blockIdx.x * 256 + threadIdx.x;   // 0..2047 -> (b, c)
    int b = idx >> 9, c = idx & 511;
    const float* x = g_analog + (size_t)b * T_ * C_ + c;
    float* o = out + (size_t)b * T_ * C_ + c;

    float vm = 0.f, ad = 0.f;
    #pragma unroll 4
    for (int t = 0; t < T_; t++) {
        float xt = x[(size_t)t * C_];
        vm = 0.9f * vm + xt;
        float th = 1.0f + 0.1f * ad;
        float u = vm - th;
        float sp = (u > 0.0f) ? 1.0f : 0.0f;
        vm = vm - sp * th;
        ad = 0.9f * ad + sp;
        o[(size_t)t * C_] = sp;
    }
}

// ------------------- launch -------------------
extern "C" void kernel_launch(void* const* d_in, const int* in_sizes, int n_in,
                              void* d_out, int out_size)
{
    const float* x     = (const float*)d_in[0];
    const float* Wq    = (const float*)d_in[1];
    const float* bq    = (const float*)d_in[2];
    const float* Wk    = (const float*)d_in[3];
    const float* bk    = (const float*)d_in[4];
    const float* Wv    = (const float*)d_in[5];
    const float* bv    = (const float*)d_in[6];
    const float* Wo    = (const float*)d_in[7];
    const float* bo    = (const float*)d_in[8];
    const float* gamma = (const float*)d_in[9];
    const float* beta  = (const float*)d_in[10];

    float* out      = (float*)d_out;
    float* out_attn = out + SPIKES_SZ;

    const int smem_gemm = (2 * 128 * 33 + 2 * 32 * 128) * 4;   // 66560 B
    cudaFuncSetAttribute(k_gemm<0>, cudaFuncAttributeMaxDynamicSharedMemorySize, smem_gemm);
    cudaFuncSetAttribute(k_gemm<1>, cudaFuncAttributeMaxDynamicSharedMemorySize, smem_gemm);

    // 1) QKV projections -> g_q/g_k/g_v in [bh][t][d] layout
    k_gemm<0><<<dim3(4, 64, 3), 256, smem_gemm>>>(x, Wq, Wk, Wv, bq, bk, bv);

    // 2) scores = Q K^T * scale (batched over 32 bh) + zero-fill attn output
    const int smem_scores = 2 * 128 * 65 * 4;
    cudaFuncSetAttribute(k_scores, cudaFuncAttributeMaxDynamicSharedMemorySize, smem_scores);
    k_scores<<<dim3(16, 16, 32), 256, smem_scores>>>(out_attn);

    // 3) top-32 + softmax + scatter into attn output
    k_topk<<<ROWS_ / 8, 256>>>(out_attn);

    // 4) sparse context
    k_context<<<ROWS_ / 8, 256>>>();

    // 5) out projection -> g_analog
    k_gemm<1><<<dim3(4, 64, 1), 256, smem_gemm>>>(nullptr, Wo, Wo, Wo, bo, bo, bo);

    // 6) layernorm (in place)
    k_ln<<<(B_ * T_) / 8, 256>>>(gamma, beta);

    // 7) LIF readout -> spikes output
    k_lif<<<8, 256>>>(out);
}

// round 7
// speedup vs baseline: 2.4077x; 1.5829x over previous
#include <cuda_runtime.h>
#include <math.h>
#include <stdint.h>

#define B_ 4
#define T_ 2048
#define C_ 512
#define H_ 8
#define HD_ 64
#define TOPK_ 32
#define BH_ (B_*H_)          // 32
#define ROWS_ (BH_*T_)       // 65536
#define SPIKES_SZ ((size_t)B_*T_*C_)   // 4194304

// ------------------- scratch (device globals; no allocation) -------------------
__device__ float g_q[BH_*T_*HD_];        // [bh][t][d]
__device__ float g_k[BH_*T_*HD_];
__device__ float g_v[BH_*T_*HD_];
__device__ float g_scores[(size_t)ROWS_*T_];   // 537MB [row][tk]
__device__ float g_topv[ROWS_*TOPK_];
__device__ int   g_topi[ROWS_*TOPK_];
__device__ float g_ctx[B_*T_*C_];        // [b][t][c]
__device__ float g_analog[B_*T_*C_];

// ------------------- GEMM: M=8192, N=512, K=512 (round-1 proven version) -------------------
// MODE 0: qkv projections (3 z-slices, head-layout epilogue)
// MODE 1: out projection (g_ctx @ Wo + bo -> g_analog)
template<int MODE>
__global__ void __launch_bounds__(256) k_gemm(const float* __restrict__ X,
    const float* __restrict__ Wq, const float* __restrict__ Wk, const float* __restrict__ Wv,
    const float* __restrict__ bq, const float* __restrict__ bk, const float* __restrict__ bv)
{
    __shared__ float As[128][33];
    __shared__ float Bs[32][128];

    const float* Xp   = (MODE == 0) ? X : g_ctx;
    const float* W    = (MODE == 0) ? (blockIdx.z == 0 ? Wq : (blockIdx.z == 1 ? Wk : Wv)) : Wq;
    const float* bias = (MODE == 0) ? (blockIdx.z == 0 ? bq : (blockIdx.z == 1 ? bk : bv)) : bq;
    float* O = 0;
    if (MODE == 0) O = (blockIdx.z == 0 ? g_q : (blockIdx.z == 1 ? g_k : g_v));
    else           O = g_analog;

    const int tid = threadIdx.x;
    const int tx = tid & 15, ty = tid >> 4;
    const int m0 = blockIdx.y * 128, n0 = blockIdx.x * 128;

    float acc[8][8];
    #pragma unroll
    for (int j = 0; j < 8; j++)
        #pragma unroll
        for (int i = 0; i < 8; i++) acc[j][i] = 0.0f;

    for (int k0 = 0; k0 < 512; k0 += 32) {
        // A tile: 128x32 (scalar stores, stride 33 -> conflict free)
        #pragma unroll
        for (int it = 0; it < 4; it++) {
            int f4 = tid + 256 * it;
            int r = f4 >> 3, c4 = f4 & 7;
            float4 v = *(const float4*)&Xp[(size_t)(m0 + r) * 512 + k0 + c4 * 4];
            As[r][c4*4+0] = v.x; As[r][c4*4+1] = v.y; As[r][c4*4+2] = v.z; As[r][c4*4+3] = v.w;
        }
        // B tile: 32x128, vectorized stores
        #pragma unroll
        for (int it = 0; it < 4; it++) {
            int f4 = tid + 256 * it;
            int r = f4 >> 5, c4 = f4 & 31;
            *(float4*)&Bs[r][c4*4] = *(const float4*)&W[(size_t)(k0 + r) * 512 + n0 + c4 * 4];
        }
        __syncthreads();

        #pragma unroll 8
        for (int kk = 0; kk < 32; kk++) {
            float a[8], b[8];
            #pragma unroll
            for (int j = 0; j < 8; j++) a[j] = As[ty + 16*j][kk];
            #pragma unroll
            for (int i = 0; i < 8; i++) b[i] = Bs[kk][tx + 16*i];
            #pragma unroll
            for (int j = 0; j < 8; j++)
                #pragma unroll
                for (int i = 0; i < 8; i++)
                    acc[j][i] += a[j] * b[i];
        }
        __syncthreads();
    }

    #pragma unroll
    for (int j = 0; j < 8; j++) {
        int m = m0 + ty + 16*j;
        #pragma unroll
        for (int i = 0; i < 8; i++) {
            int n = n0 + tx + 16*i;
            float val = acc[j][i] + bias[n];
            if (MODE == 0) {
                int b = m >> 11, t = m & 2047;
                int h = n >> 6, d = n & 63;
                O[(((size_t)(b * H_ + h)) * T_ + t) * HD_ + d] = val;
            } else {
                O[(size_t)m * 512 + n] = val;
            }
        }
    }
}

// ------------------- scores: per-bh 2048x2048x64 GEMM, *SCALE, + attn zero-fill -------------------
__global__ void __launch_bounds__(256) k_scores(float* __restrict__ attn_out)
{
    extern __shared__ float sm[];
    float (*Qs)[65] = (float(*)[65])sm;               // 128 x 65
    float (*Ks)[65] = (float(*)[65])(sm + 128 * 65);  // 128 x 65

    const int bh = blockIdx.z;
    const float* Qb = g_q + (size_t)bh * T_ * HD_;
    const float* Kb = g_k + (size_t)bh * T_ * HD_;
    const int tid = threadIdx.x;
    const int tx = tid & 15, ty = tid >> 4;
    const int m0 = blockIdx.y * 128, n0 = blockIdx.x * 128;

    #pragma unroll
    for (int it = 0; it < 8; it++) {   // 2048 float4 per tile
        int f4 = tid + 256 * it;
        int r = f4 >> 4, c4 = f4 & 15;
        float4 v = *(const float4*)&Qb[(size_t)(m0 + r) * 64 + c4 * 4];
        Qs[r][c4*4+0] = v.x; Qs[r][c4*4+1] = v.y; Qs[r][c4*4+2] = v.z; Qs[r][c4*4+3] = v.w;
        float4 w = *(const float4*)&Kb[(size_t)(n0 + r) * 64 + c4 * 4];
        Ks[r][c4*4+0] = w.x; Ks[r][c4*4+1] = w.y; Ks[r][c4*4+2] = w.z; Ks[r][c4*4+3] = w.w;
    }
    __syncthreads();

    float acc[8][8];
    #pragma unroll
    for (int j = 0; j < 8; j++)
        #pragma unroll
        for (int i = 0; i < 8; i++) acc[j][i] = 0.0f;

    #pragma unroll 8
    for (int d = 0; d < 64; d++) {
        float a[8], b[8];
        #pragma unroll
        for (int j = 0; j < 8; j++) a[j] = Qs[ty + 16*j][d];
        #pragma unroll
        for (int i = 0; i < 8; i++) b[i] = Ks[tx + 16*i][d];
        #pragma unroll
        for (int j = 0; j < 8; j++)
            #pragma unroll
            for (int i = 0; i < 8; i++)
                acc[j][i] += a[j] * b[i];
    }

    float* Sb = g_scores + (size_t)bh * T_ * T_;
    const float4 z = make_float4(0.f, 0.f, 0.f, 0.f);
    #pragma unroll
    for (int j = 0; j < 8; j++) {
        int m = m0 + ty + 16*j;
        #pragma unroll
        for (int i = 0; i < 8; i++) {
            int n = n0 + tx + 16*i;
            Sb[(size_t)m * T_ + n] = acc[j][i] * 0.125f;
        }
        // zero-fill this block's tile of the attn output (hidden under GEMM compute)
        size_t grow = (size_t)(bh * T_ + m);
        float4* dst = (float4*)(attn_out + grow * T_ + n0);
        dst[tx*2]   = z;
        dst[tx*2+1] = z;
    }
}

// ------------------- top-32 + softmax + scatter (one warp per row, MLP=8 prefetch) -------------------
__global__ void __launch_bounds__(256) k_topk(float* __restrict__ attn_out)
{
    const unsigned FULL = 0xffffffffu;
    int warp = threadIdx.x >> 5, lane = threadIdx.x & 31;
    int row = blockIdx.x * 8 + warp;
    const float* r = g_scores + (size_t)row * T_;

    float lv = -INFINITY;  // lane holds slot `lane` of descending sorted top-32
    int   li = 0;

    for (int cb = 0; cb < 64; cb += 8) {
        float e8[8];
        #pragma unroll
        for (int j = 0; j < 8; j++) e8[j] = r[(cb + j) * 32 + lane];   // 8 loads in flight

        #pragma unroll
        for (int j = 0; j < 8; j++) {
            float e = e8[j];
            int idx = (cb + j) * 32 + lane;
            float thr = __shfl_sync(FULL, lv, 31);        // current min of list
            unsigned mask = __ballot_sync(FULL, e > thr);
            while (mask) {
                int src = __ffs(mask) - 1;
                mask &= mask - 1;
                float xv = __shfl_sync(FULL, e, src);
                int   xi = __shfl_sync(FULL, idx, src);
                unsigned ge = __ballot_sync(FULL, lv >= xv);   // entries ranked above x (stable)
                int pos = __popc(ge);
                float pv = __shfl_up_sync(FULL, lv, 1);
                int   pi = __shfl_up_sync(FULL, li, 1);
                if (lane >= pos) {
                    lv = (lane == pos) ? xv : pv;
                    li = (lane == pos) ? xi : pi;
                }
            }
        }
    }

    // softmax over the 32 selected values (lane 0 holds the max)
    float mx = __shfl_sync(FULL, lv, 0);
    float p = expf(lv - mx);
    float s = p;
    #pragma unroll
    for (int o = 16; o; o >>= 1) s += __shfl_xor_sync(FULL, s, o);
    p /= s;

    g_topv[row * 32 + lane] = p;
    g_topi[row * 32 + lane] = li;

    // row already zeroed by k_scores; just scatter
    attn_out[(size_t)row * T_ + li] = p;
}

// ------------------- sparse context gather (one warp per row) -------------------
__global__ void __launch_bounds__(256) k_context()
{
    const unsigned FULL = 0xffffffffu;
    int warp = threadIdx.x >> 5, lane = threadIdx.x & 31;
    int row = blockIdx.x * 8 + warp;
    int bh = row >> 11, t = row & 2047;
    const float* Vb = g_v + (size_t)bh * T_ * HD_;

    float pj = g_topv[row * 32 + lane];
    int   ij = g_topi[row * 32 + lane];
    float a0 = 0.f, a1 = 0.f;
    #pragma unroll
    for (int j = 0; j < 32; j++) {
        float p = __shfl_sync(FULL, pj, j);
        int  ix = __shfl_sync(FULL, ij, j);
        const float* vr = Vb + (size_t)ix * HD_;
        a0 += p * vr[lane];
        a1 += p * vr[lane + 32];
    }
    int b = bh >> 3, h = bh & 7;
    float* o = g_ctx + ((size_t)(b * T_ + t)) * C_ + h * HD_;
    o[lane] = a0;
    o[lane + 32] = a1;
}

// ------------------- LayerNorm (two-pass, warp per row) -------------------
__global__ void __launch_bounds__(256) k_ln(const float* __restrict__ gamma,
                                            const float* __restrict__ beta)
{
    const unsigned FULL = 0xffffffffu;
    int warp = threadIdx.x >> 5, lane = threadIdx.x & 31;
    int row = blockIdx.x * 8 + warp;
    const float* x = g_analog + (size_t)row * C_;

    float v[16];
    float s = 0.f;
    #pragma unroll
    for (int i = 0; i < 16; i++) { v[i] = x[lane + 32 * i]; s += v[i]; }
    #pragma unroll
    for (int o = 16; o; o >>= 1) s += __shfl_xor_sync(FULL, s, o);
    float mu = s * (1.0f / 512.0f);

    float q = 0.f;
    #pragma unroll
    for (int i = 0; i < 16; i++) { float d = v[i] - mu; q += d * d; }
    #pragma unroll
    for (int o = 16; o; o >>= 1) q += __shfl_xor_sync(FULL, q, o);
    float var = q * (1.0f / 512.0f);
    float inv = 1.0f / sqrtf(var + 1e-5f);

    float* y = g_analog + (size_t)row * C_;
    #pragma unroll
    for (int i = 0; i < 16; i++) {
        int c = lane + 32 * i;
        y[c] = (v[i] - mu) * inv * gamma[c] + beta[c];
    }
}

// ------------------- adaptive LIF readout (one thread per (b,c) chain) -------------------
__global__ void __launch_bounds__(256) k_lif(float* __restrict__ out)
{
    int idx = blockIdx.x * 256 + threadIdx.x;   // 0..2047 -> (b, c)
    int b = idx >> 9, c = idx & 511;
    const float* x = g_analog + (size_t)b * T_ * C_ + c;
    float* o = out + (size_t)b * T_ * C_ + c;

    float vm = 0.f, ad = 0.f;
    #pragma unroll 4
    for (int t = 0; t < T_; t++) {
        float xt = x[(size_t)t * C_];
        vm = 0.9f * vm + xt;
        float th = 1.0f + 0.1f * ad;
        float u = vm - th;
        float sp = (u > 0.0f) ? 1.0f : 0.0f;
        vm = vm - sp * th;
        ad = 0.9f * ad + sp;
        o[(size_t)t * C_] = sp;
    }
}

// ------------------- launch -------------------
extern "C" void kernel_launch(void* const* d_in, const int* in_sizes, int n_in,
                              void* d_out, int out_size)
{
    const float* x     = (const float*)d_in[0];
    const float* Wq    = (const float*)d_in[1];
    const float* bq    = (const float*)d_in[2];
    const float* Wk    = (const float*)d_in[3];
    const float* bk    = (const float*)d_in[4];
    const float* Wv    = (const float*)d_in[5];
    const float* bv    = (const float*)d_in[6];
    const float* Wo    = (const float*)d_in[7];
    const float* bo    = (const float*)d_in[8];
    const float* gamma = (const float*)d_in[9];
    const float* beta  = (const float*)d_in[10];

    float* out      = (float*)d_out;
    float* out_attn = out + SPIKES_SZ;

    // 1) QKV projections -> g_q/g_k/g_v in [bh][t][d] layout
    k_gemm<0><<<dim3(4, 64, 3), 256>>>(x, Wq, Wk, Wv, bq, bk, bv);

    // 2) scores = Q K^T * scale (batched over 32 bh) + zero-fill attn output
    const int smem_scores = 2 * 128 * 65 * 4;
    cudaFuncSetAttribute(k_scores, cudaFuncAttributeMaxDynamicSharedMemorySize, smem_scores);
    k_scores<<<dim3(16, 16, 32), 256, smem_scores>>>(out_attn);

    // 3) top-32 + softmax + scatter into attn output
    k_topk<<<ROWS_ / 8, 256>>>(out_attn);

    // 4) sparse context
    k_context<<<ROWS_ / 8, 256>>>();

    // 5) out projection -> g_analog
    k_gemm<1><<<dim3(4, 64, 1), 256>>>(nullptr, Wo, Wo, Wo, bo, bo, bo);

    // 6) layernorm (in place)
    k_ln<<<(B_ * T_) / 8, 256>>>(gamma, beta);

    // 7) LIF readout -> spikes output
    k_lif<<<8, 256>>>(out);
}

// round 8
// speedup vs baseline: 2.4354x; 1.0115x over previous
#include <cuda_runtime.h>
#include <math.h>
#include <stdint.h>

#define B_ 4
#define T_ 2048
#define C_ 512
#define H_ 8
#define HD_ 64
#define TOPK_ 32
#define BH_ (B_*H_)          // 32
#define ROWS_ (BH_*T_)       // 65536
#define SPIKES_SZ ((size_t)B_*T_*C_)   // 4194304

// ------------------- cp.async helpers -------------------
__device__ __forceinline__ void cp_async16(void* smem_dst, const void* gsrc) {
    unsigned dst = (unsigned)__cvta_generic_to_shared(smem_dst);
    asm volatile("cp.async.cg.shared.global [%0], [%1], 16;" :: "r"(dst), "l"(gsrc));
}
__device__ __forceinline__ void cp_commit() {
    asm volatile("cp.async.commit_group;");
}
template<int N>
__device__ __forceinline__ void cp_wait() {
    asm volatile("cp.async.wait_group %0;" :: "n"(N));
}

// ------------------- scratch (device globals; no allocation) -------------------
__device__ float g_q[BH_*T_*HD_];        // [bh][t][d]
__device__ float g_k[BH_*T_*HD_];
__device__ float g_v[BH_*T_*HD_];
__device__ float g_scores[(size_t)ROWS_*T_];   // 537MB [row][tk]
__device__ float g_ctx[B_*T_*C_];        // [b][t][c]
__device__ float g_analog[B_*T_*C_];

// ------------------- GEMM: M=8192, N=512, K=512, cp.async double-buffered -------------------
// A-tile stride 36 floats (144B: 16B-aligned rows for cp.async; a-reads are ty-broadcast).
// MODE 0: qkv projections (3 z-slices, head-layout epilogue)
// MODE 1: out projection (g_ctx @ Wo + bo -> g_analog)
#define A_STRIDE 36
template<int MODE>
__global__ void __launch_bounds__(256) k_gemm(const float* __restrict__ X,
    const float* __restrict__ Wq, const float* __restrict__ Wk, const float* __restrict__ Wv,
    const float* __restrict__ bq, const float* __restrict__ bk, const float* __restrict__ bv)
{
    extern __shared__ float smg[];
    float (*As)[128][A_STRIDE] = (float(*)[128][A_STRIDE])smg;                 // 2 x 128 x 36
    float (*Bs)[32][128]       = (float(*)[32][128])(smg + 2*128*A_STRIDE);    // 2 x 32 x 128

    const float* Xp   = (MODE == 0) ? X : g_ctx;
    const float* W    = (MODE == 0) ? (blockIdx.z == 0 ? Wq : (blockIdx.z == 1 ? Wk : Wv)) : Wq;
    const float* bias = (MODE == 0) ? (blockIdx.z == 0 ? bq : (blockIdx.z == 1 ? bk : bv)) : bq;
    float* O = 0;
    if (MODE == 0) O = (blockIdx.z == 0 ? g_q : (blockIdx.z == 1 ? g_k : g_v));
    else           O = g_analog;

    const int tid = threadIdx.x;
    const int tx = tid & 15, ty = tid >> 4;
    const int m0 = blockIdx.y * 128, n0 = blockIdx.x * 128;

    float acc[8][8];
    #pragma unroll
    for (int j = 0; j < 8; j++)
        #pragma unroll
        for (int i = 0; i < 8; i++) acc[j][i] = 0.0f;

    // tile prefetch: 4 A-chunks + 4 B-chunks per thread, 16B each
    auto prefetch = [&](int k0, int buf) {
        #pragma unroll
        for (int it = 0; it < 4; it++) {
            int f4 = tid + 256 * it;
            int r = f4 >> 3, c = f4 & 7;
            cp_async16(&As[buf][r][c*4], &Xp[(size_t)(m0 + r) * 512 + k0 + c * 4]);
        }
        #pragma unroll
        for (int it = 0; it < 4; it++) {
            int f4 = tid + 256 * it;
            int r = f4 >> 5, c4 = f4 & 31;
            cp_async16(&Bs[buf][r][c4*4], &W[(size_t)(k0 + r) * 512 + n0 + c4 * 4]);
        }
        cp_commit();
    };

    prefetch(0, 0);

    for (int t = 0; t < 16; t++) {
        const int buf = t & 1;
        if (t < 15) {
            prefetch((t + 1) * 32, buf ^ 1);
            cp_wait<1>();           // tile t landed
        } else {
            cp_wait<0>();
        }
        __syncthreads();

        #pragma unroll 8
        for (int kk = 0; kk < 32; kk++) {
            float a[8], b[8];
            #pragma unroll
            for (int j = 0; j < 8; j++) a[j] = As[buf][ty + 16*j][kk];
            #pragma unroll
            for (int i = 0; i < 8; i++) b[i] = Bs[buf][kk][tx + 16*i];
            #pragma unroll
            for (int j = 0; j < 8; j++)
                #pragma unroll
                for (int i = 0; i < 8; i++)
                    acc[j][i] += a[j] * b[i];
        }
        __syncthreads();            // all warps done with buf before t+1 iter overwrites it
    }

    #pragma unroll
    for (int j = 0; j < 8; j++) {
        int m = m0 + ty + 16*j;
        #pragma unroll
        for (int i = 0; i < 8; i++) {
            int n = n0 + tx + 16*i;
            float val = acc[j][i] + bias[n];
            if (MODE == 0) {
                int b = m >> 11, t = m & 2047;
                int h = n >> 6, d = n & 63;
                O[(((size_t)(b * H_ + h)) * T_ + t) * HD_ + d] = val;
            } else {
                O[(size_t)m * 512 + n] = val;
            }
        }
    }
}

// ------------------- scores: per-bh 2048x2048x64 GEMM, *SCALE, + attn zero-fill -------------------
__global__ void __launch_bounds__(256) k_scores(float* __restrict__ attn_out)
{
    extern __shared__ float sm[];
    float (*Qs)[65] = (float(*)[65])sm;               // 128 x 65
    float (*Ks)[65] = (float(*)[65])(sm + 128 * 65);  // 128 x 65

    const int bh = blockIdx.z;
    const float* Qb = g_q + (size_t)bh * T_ * HD_;
    const float* Kb = g_k + (size_t)bh * T_ * HD_;
    const int tid = threadIdx.x;
    const int tx = tid & 15, ty = tid >> 4;
    const int m0 = blockIdx.y * 128, n0 = blockIdx.x * 128;

    #pragma unroll
    for (int it = 0; it < 8; it++) {   // 2048 float4 per tile
        int f4 = tid + 256 * it;
        int r = f4 >> 4, c4 = f4 & 15;
        float4 v = *(const float4*)&Qb[(size_t)(m0 + r) * 64 + c4 * 4];
        Qs[r][c4*4+0] = v.x; Qs[r][c4*4+1] = v.y; Qs[r][c4*4+2] = v.z; Qs[r][c4*4+3] = v.w;
        float4 w = *(const float4*)&Kb[(size_t)(n0 + r) * 64 + c4 * 4];
        Ks[r][c4*4+0] = w.x; Ks[r][c4*4+1] = w.y; Ks[r][c4*4+2] = w.z; Ks[r][c4*4+3] = w.w;
    }
    __syncthreads();

    float acc[8][8];
    #pragma unroll
    for (int j = 0; j < 8; j++)
        #pragma unroll
        for (int i = 0; i < 8; i++) acc[j][i] = 0.0f;

    #pragma unroll 8
    for (int d = 0; d < 64; d++) {
        float a[8], b[8];
        #pragma unroll
        for (int j = 0; j < 8; j++) a[j] = Qs[ty + 16*j][d];
        #pragma unroll
        for (int i = 0; i < 8; i++) b[i] = Ks[tx + 16*i][d];
        #pragma unroll
        for (int j = 0; j < 8; j++)
            #pragma unroll
            for (int i = 0; i < 8; i++)
                acc[j][i] += a[j] * b[i];
    }

    float* Sb = g_scores + (size_t)bh * T_ * T_;
    const float4 z = make_float4(0.f, 0.f, 0.f, 0.f);
    #pragma unroll
    for (int j = 0; j < 8; j++) {
        int m = m0 + ty + 16*j;
        #pragma unroll
        for (int i = 0; i < 8; i++) {
            int n = n0 + tx + 16*i;
            Sb[(size_t)m * T_ + n] = acc[j][i] * 0.125f;
        }
        // zero-fill this block's tile of the attn output (hidden under GEMM compute)
        size_t grow = (size_t)(bh * T_ + m);
        float4* dst = (float4*)(attn_out + grow * T_ + n0);
        dst[tx*2]   = z;
        dst[tx*2+1] = z;
    }
}

// ------------------- fused top-32 + softmax + scatter + context gather -------------------
// one warp per row; MLP=8 prefetch; V-gather runs on the warp's register-resident top list
__global__ void __launch_bounds__(256) k_topkctx(float* __restrict__ attn_out)
{
    const unsigned FULL = 0xffffffffu;
    int warp = threadIdx.x >> 5, lane = threadIdx.x & 31;
    int row = blockIdx.x * 8 + warp;
    const float* r = g_scores + (size_t)row * T_;

    float lv = -INFINITY;  // lane holds slot `lane` of descending sorted top-32
    int   li = 0;

    for (int cb = 0; cb < 64; cb += 8) {
        float e8[8];
        #pragma unroll
        for (int j = 0; j < 8; j++) e8[j] = r[(cb + j) * 32 + lane];   // 8 loads in flight

        #pragma unroll
        for (int j = 0; j < 8; j++) {
            float e = e8[j];
            int idx = (cb + j) * 32 + lane;
            float thr = __shfl_sync(FULL, lv, 31);        // current min of list
            unsigned mask = __ballot_sync(FULL, e > thr);
            while (mask) {
                int src = __ffs(mask) - 1;
                mask &= mask - 1;
                float xv = __shfl_sync(FULL, e, src);
                int   xi = __shfl_sync(FULL, idx, src);
                unsigned ge = __ballot_sync(FULL, lv >= xv);   // entries ranked above x (stable)
                int pos = __popc(ge);
                float pv = __shfl_up_sync(FULL, lv, 1);
                int   pi = __shfl_up_sync(FULL, li, 1);
                if (lane >= pos) {
                    lv = (lane == pos) ? xv : pv;
                    li = (lane == pos) ? xi : pi;
                }
            }
        }
    }

    // softmax over the 32 selected values (lane 0 holds the max)
    float mx = __shfl_sync(FULL, lv, 0);
    float p = expf(lv - mx);
    float s = p;
    #pragma unroll
    for (int o = 16; o; o >>= 1) s += __shfl_xor_sync(FULL, s, o);
    p /= s;

    // scatter into attn output (row already zeroed by k_scores)
    attn_out[(size_t)row * T_ + li] = p;

    // context gather: identical arithmetic order to the former k_context
    int bh = row >> 11, t = row & 2047;
    const float* Vb = g_v + (size_t)bh * T_ * HD_;
    float a0 = 0.f, a1 = 0.f;
    #pragma unroll
    for (int j = 0; j < 32; j++) {
        float pp = __shfl_sync(FULL, p, j);
        int   ix = __shfl_sync(FULL, li, j);
        const float* vr = Vb + (size_t)ix * HD_;
        a0 += pp * vr[lane];
        a1 += pp * vr[lane + 32];
    }
    int b = bh >> 3, h = bh & 7;
    float* o = g_ctx + ((size_t)(b * T_ + t)) * C_ + h * HD_;
    o[lane] = a0;
    o[lane + 32] = a1;
}

// ------------------- LayerNorm (two-pass, warp per row) -------------------
__global__ void __launch_bounds__(256) k_ln(const float* __restrict__ gamma,
                                            const float* __restrict__ beta)
{
    const unsigned FULL = 0xffffffffu;
    int warp = threadIdx.x >> 5, lane = threadIdx.x & 31;
    int row = blockIdx.x * 8 + warp;
    const float* x = g_analog + (size_t)row * C_;

    float v[16];
    float s = 0.f;
    #pragma unroll
    for (int i = 0; i < 16; i++) { v[i] = x[lane + 32 * i]; s += v[i]; }
    #pragma unroll
    for (int o = 16; o; o >>= 1) s += __shfl_xor_sync(FULL, s, o);
    float mu = s * (1.0f / 512.0f);

    float q = 0.f;
    #pragma unroll
    for (int i = 0; i < 16; i++) { float d = v[i] - mu; q += d * d; }
    #pragma unroll
    for (int o = 16; o; o >>= 1) q += __shfl_xor_sync(FULL, q, o);
    float var = q * (1.0f / 512.0f);
    float inv = 1.0f / sqrtf(var + 1e-5f);

    float* y = g_analog + (size_t)row * C_;
    #pragma unroll
    for (int i = 0; i < 16; i++) {
        int c = lane + 32 * i;
        y[c] = (v[i] - mu) * inv * gamma[c] + beta[c];
    }
}

// ------------------- adaptive LIF readout (one thread per (b,c) chain) -------------------
__global__ void __launch_bounds__(256) k_lif(float* __restrict__ out)
{
    int idx = blockIdx.x * 256 + threadIdx.x;   // 0..2047 -> (b, c)
    int b = idx >> 9, c = idx & 511;
    const float* x = g_analog + (size_t)b * T_ * C_ + c;
    float* o = out + (size_t)b * T_ * C_ + c;

    float vm = 0.f, ad = 0.f;
    #pragma unroll 4
    for (int t = 0; t < T_; t++) {
        float xt = x[(size_t)t * C_];
        vm = 0.9f * vm + xt;
        float th = 1.0f + 0.1f * ad;
        float u = vm - th;
        float sp = (u > 0.0f) ? 1.0f : 0.0f;
        vm = vm - sp * th;
        ad = 0.9f * ad + sp;
        o[(size_t)t * C_] = sp;
    }
}

// ------------------- launch -------------------
extern "C" void kernel_launch(void* const* d_in, const int* in_sizes, int n_in,
                              void* d_out, int out_size)
{
    const float* x     = (const float*)d_in[0];
    const float* Wq    = (const float*)d_in[1];
    const float* bq    = (const float*)d_in[2];
    const float* Wk    = (const float*)d_in[3];
    const float* bk    = (const float*)d_in[4];
    const float* Wv    = (const float*)d_in[5];
    const float* bv    = (const float*)d_in[6];
    const float* Wo    = (const float*)d_in[7];
    const float* bo    = (const float*)d_in[8];
    const float* gamma = (const float*)d_in[9];
    const float* beta  = (const float*)d_in[10];

    float* out      = (float*)d_out;
    float* out_attn = out + SPIKES_SZ;

    const int smem_gemm = (2 * 128 * A_STRIDE + 2 * 32 * 128) * 4;   // 69632 B
    cudaFuncSetAttribute(k_gemm<0>, cudaFuncAttributeMaxDynamicSharedMemorySize, smem_gemm);
    cudaFuncSetAttribute(k_gemm<1>, cudaFuncAttributeMaxDynamicSharedMemorySize, smem_gemm);

    // 1) QKV projections -> g_q/g_k/g_v in [bh][t][d] layout
    k_gemm<0><<<dim3(4, 64, 3), 256, smem_gemm>>>(x, Wq, Wk, Wv, bq, bk, bv);

    // 2) scores = Q K^T * scale (batched over 32 bh) + zero-fill attn output
    const int smem_scores = 2 * 128 * 65 * 4;
    cudaFuncSetAttribute(k_scores, cudaFuncAttributeMaxDynamicSharedMemorySize, smem_scores);
    k_scores<<<dim3(16, 16, 32), 256, smem_scores>>>(out_attn);

    // 3) fused top-32 + softmax + scatter + context gather
    k_topkctx<<<ROWS_ / 8, 256>>>(out_attn);

    // 4) out projection -> g_analog
    k_gemm<1><<<dim3(4, 64, 1), 256, smem_gemm>>>(nullptr, Wo, Wo, Wo, bo, bo, bo);

    // 5) layernorm (in place)
    k_ln<<<(B_ * T_) / 8, 256>>>(gamma, beta);

    // 6) LIF readout -> spikes output
    k_lif<<<8, 256>>>(out);
}